// round 17
// baseline (speedup 1.0000x reference)
#include <cuda_runtime.h>
#include <math.h>

// Problem dims (fixed)
#define Bsz   128
#define Tlen  512
#define Isz   256
#define Hsz   512
#define Osz   256

// Pod decomposition: 16 independent pods x 8 blocks; each pod owns 8 batches,
// each block owns 64 h-rows of W_hh (k-major, 132KB fp32 in smem).
#define PODS  16
#define PODB  8      // blocks per pod
#define PB    8      // batches per pod
#define NBT   8      // xp batch tiles (of 16)
#define WROW  516    // padded W row stride (floats)

// Packed f32x2 helpers (ptxas never emits FFMA2 from C++; inline PTX required)
#define FMA2(acc, a, b) \
    asm("fma.rn.f32x2 %0, %1, %2, %0;" : "+l"(acc) : "l"(a), "l"(b))
#define ADD2(d, a, b) \
    asm("add.rn.f32x2 %0, %1, %2;" : "=l"(d) : "l"(a), "l"(b))
#define PACK2(d, lo, hi) \
    asm("mov.b64 %0, {%1, %2};" : "=l"(d) : "f"(lo), "f"(hi))
#define UNPACK2(lo, hi, v) \
    asm("mov.b64 {%0, %1}, %2;" : "=f"(lo), "=f"(hi) : "l"(v))

typedef unsigned long long u64;

__device__ __forceinline__ unsigned ldv(const unsigned* p) {
    unsigned v;
    asm volatile("ld.volatile.global.u32 %0, [%1];" : "=r"(v) : "l"(p));
    return v;
}

// Scratch (device globals; no runtime allocation)
__device__ float    g_xp[(size_t)Tlen * PODS * PB * Hsz]; // [t][pod][b][h]
__device__ float    g_hp[2][PODS * PB * Hsz];             // [parity][pod][b][k]
__device__ unsigned g_flag[PODS * PODB * 32];             // 128B-padded per (pod,chunk)

// ---------------------------------------------------------------------------
// x_proj: xp[t][pod][b][h] = sum_i inputs[b][t][i]*W_ih[h][i] + b_ih[h]+b_hh[h]
// Block (0,0,0) also zeroes the producer flags (stream-ordered before rnn).
// ---------------------------------------------------------------------------
#define TQ  8
#define XSROW 257

__global__ void __launch_bounds__(256) xp_kernel(
    const float* __restrict__ inputs, const float* __restrict__ W_ih,
    const float* __restrict__ b_ih,   const float* __restrict__ b_hh)
{
    extern __shared__ float smem[];
    float* Wt  = smem;                              // [256][32]: Wt[i][j]=W_ih[h0+j][i]
    u64*   xs2 = (u64*)(smem + 8192);               // [16][257]: xs2[b][i]={x,x}
    u64*   red = (u64*)(smem + 8192 + 2 * 16 * XSROW);  // [4][16][16]
    const u64* Wtu = (const u64*)Wt;

    const int tq = blockIdx.x, bt = blockIdx.y, ht = blockIdx.z;
    const int h0 = ht * 32, b0 = bt * 16;
    const int tid = threadIdx.x;

    // Zero rnn producer flags (one block; kernel boundary orders vs rnn)
    if (tq == 0 && bt == 0 && ht == 0) {
        for (int i = tid; i < PODS * PODB * 32; i += 256) g_flag[i] = 0;
    }

    // Stage W_ih tile transposed (once)
    {
        const int lane_j = tid & 31, qb = tid >> 5;          // qb 0..7
        for (int r = 0; r < 8; r++) {
            int q = qb + 8 * r;                              // 0..63
            float4 w = *(const float4*)&W_ih[(h0 + lane_j) * Isz + 4 * q];
            Wt[(4*q+0)*32 + lane_j] = w.x;
            Wt[(4*q+1)*32 + lane_j] = w.y;
            Wt[(4*q+2)*32 + lane_j] = w.z;
            Wt[(4*q+3)*32 + lane_j] = w.w;
        }
    }

    const int bg = tid & 7, hg = (tid >> 3) & 7, is = tid >> 6;  // I-split 4
    const int pb = tid & 15, php = tid >> 4;                     // phase-2 roles
    const int pod = bt * 2 + (pb >> 3), bi = pb & 7;
    const float pbias0 = b_ih[h0 + php*2 + 0] + b_hh[h0 + php*2 + 0];
    const float pbias1 = b_ih[h0 + php*2 + 1] + b_hh[h0 + php*2 + 1];

    for (int tt = 0; tt < TQ; tt++) {
        const int t = tq * TQ + tt;
        __syncthreads();   // xs2/red reuse; covers Wt on first iter
        for (int j = 0; j < 4; j++) {
            int idx = tid + 256 * j;                 // 1024 float4 loads
            int r = idx >> 6, q = idx & 63;
            float4 x = *(const float4*)&inputs[((size_t)(b0 + r) * Tlen + t) * Isz + 4 * q];
            u64 p0, p1, p2, p3;
            PACK2(p0, x.x, x.x); PACK2(p1, x.y, x.y);
            PACK2(p2, x.z, x.z); PACK2(p3, x.w, x.w);
            u64* dst = &xs2[r * XSROW + 4 * q];
            dst[0] = p0; dst[1] = p1; dst[2] = p2; dst[3] = p3;
        }
        __syncthreads();

        u64 a00 = 0, a10 = 0, a01 = 0, a11 = 0;
        const u64* xr0 = &xs2[(2 * bg + 0) * XSROW + is * 64];
        const u64* xr1 = &xs2[(2 * bg + 1) * XSROW + is * 64];
        const u64* wr  = &Wtu[(is * 64) * 16 + hg * 2];
        #pragma unroll 8
        for (int ii = 0; ii < 64; ii++) {
            ulonglong2 w = *(const ulonglong2*)&wr[ii * 16];
            u64 x0 = xr0[ii];
            u64 x1 = xr1[ii];
            FMA2(a00, w.x, x0);
            FMA2(a10, w.y, x0);
            FMA2(a01, w.x, x1);
            FMA2(a11, w.y, x1);
        }
        u64* rb = &red[is * 256 + (hg * 2) * 16 + bg * 2];
        rb[0]  = a00;
        rb[16] = a10;
        rb[1]  = a01;
        rb[17] = a11;
        __syncthreads();

        u64 s, u;
        ADD2(s, red[0*256 + php*16 + pb], red[1*256 + php*16 + pb]);
        ADD2(u, red[2*256 + php*16 + pb], red[3*256 + php*16 + pb]);
        ADD2(s, s, u);
        float v0, v1; UNPACK2(v0, v1, s);
        // b-major layout: g_xp[t][pod][b][h]
        float* dst = &g_xp[(((size_t)t * PODS + pod) * PB + bi) * Hsz + h0 + php * 2];
        dst[0] = v0 + pbias0;
        dst[1] = v1 + pbias1;
    }
}

// ---------------------------------------------------------------------------
// Persistent recurrence, zero intra-block syncs in the time loop.
// 128 blocks = 16 pods x 8; 512 threads = 16 warps.
// Warp = 16h x 2b over FULL K=512 (no K-split, no reduction, no phase 2).
// Thread = 1 output; k-packed FMA2; per 8k: 4 LDS.128 + 4 FMA2.
// Each warp privately stages its 2 b-rows of h_t (4KB) after polling all 8
// producer flags in parallel (8 lanes). Flags: atomicAdd(1) per warp ->
// flag == 16*(t+1) when a chunk is fully published.
// smem: Wk[64][516] f32 (132KB) + hsw[16 warps][2 b][512 k] f32 (64KB)
// ---------------------------------------------------------------------------
__global__ void __launch_bounds__(512) rnn_kernel(
    const float* __restrict__ W_hh, const float* __restrict__ h0g,
    const float* __restrict__ W_out, const float* __restrict__ b_out,
    float* __restrict__ out)
{
    extern __shared__ float smem[];
    float* Wk  = smem;                          // [64][WROW] k-major W rows
    float* hsw = smem + 64 * WROW;              // [16][2][512] per-warp h copies

    const int blk = blockIdx.x;
    const int pod = blk >> 3, ht = blk & 7;
    const int h0 = ht * 64;
    const int tid = threadIdx.x;
    const int lane = tid & 31;
    const int warp = tid >> 5;
    const int wh = warp >> 2;                   // h-group 0..3 (16 h each)
    const int wb = warp & 3;                    // b-pair 0..3
    const int hl = lane >> 1;                   // h within warp tile 0..15
    const int bl = lane & 1;                    // b within pair

    // Stage this block's 64-row W_hh slice, k-major with padded rows (once)
    {
        const int j = tid >> 3, ql = tid & 7;   // row 0..63, q-lane 0..7
        for (int r = 0; r < 16; r++) {
            int q = ql + 8 * r;                 // 0..127 (float4 index)
            float4 w = *(const float4*)&W_hh[(h0 + j) * Hsz + 4 * q];
            *(float4*)&Wk[j * WROW + 4 * q] = w;
        }
    }

    const int h_glob = h0 + wh * 16 + hl;       // this thread's output h row
    const int b_glob = 2 * wb + bl;             // this thread's batch (in pod)
    const float* wrow = &Wk[(wh * 16 + hl) * WROW];
    const float* hrow = &hsw[(warp * 2 + bl) * 512];
    float* hstage = &hsw[warp * 2 * 512];       // warp's 4KB staging region
    const unsigned* flagbase = &g_flag[pod * PODB * 32];
    unsigned* myflag = &g_flag[(pod * PODB + ht) * 32];
    const float invT = 1.0f / 512.0f;

    __syncthreads();   // Wk staged (only sync before the loop)

    for (int t = 0; t < Tlen; t++) {
        if (t == 0) {
            // Stage h0 into both b-rows (h0 is b-independent)
            const float4* src4 = (const float4*)h0g;
            float4* dst = (float4*)hstage;
            #pragma unroll
            for (int j = 0; j < 4; j++) {
                float4 v = src4[lane + 32 * j];
                dst[lane + 32 * j] = v;
                dst[128 + lane + 32 * j] = v;
            }
        } else {
            // Poll all 8 producer flags in parallel (lanes 0..7)
            const int target = 16 * t;
            unsigned done;
            do {
                int v = (lane < PODB) ? (int)ldv(flagbase + lane * 32) : target;
                done = __all_sync(0xffffffffu, v >= target);
            } while (!done);
            // Stage this warp's 2 b-rows of h_t (4KB), L2-sourced
            const float4* src = (const float4*)(g_hp[t & 1] + (pod * PB + 2 * wb) * Hsz);
            float4* dst = (float4*)hstage;
            #pragma unroll
            for (int j = 0; j < 8; j++)
                dst[lane + 32 * j] = __ldcg(src + lane + 32 * j);
        }
        // xp for this thread's output (b-major: coalesced 2x64B per warp)
        const float xp = __ldg(&g_xp[(((size_t)t * PODS + pod) * PB + b_glob) * Hsz + h_glob]);

        // Full-K GEMM, k-packed: per 8k: 4 LDS.128 + 4 FMA2, 4 accumulators
        u64 a0 = 0, a1 = 0, a2 = 0, a3 = 0;
        #pragma unroll 8
        for (int k8 = 0; k8 < 64; k8++) {
            ulonglong2 w0 = *(const ulonglong2*)(wrow + k8 * 8);
            ulonglong2 hv0 = *(const ulonglong2*)(hrow + k8 * 8);
            ulonglong2 w1 = *(const ulonglong2*)(wrow + k8 * 8 + 4);
            ulonglong2 hv1 = *(const ulonglong2*)(hrow + k8 * 8 + 4);
            FMA2(a0, w0.x, hv0.x);
            FMA2(a1, w0.y, hv0.y);
            FMA2(a2, w1.x, hv1.x);
            FMA2(a3, w1.y, hv1.y);
        }
        u64 s01, s23;
        ADD2(s01, a0, a1);
        ADD2(s23, a2, a3);
        ADD2(s01, s01, s23);
        float lo, hi; UNPACK2(lo, hi, s01);
        float v = lo + hi;

        // Epilogue: h_new = h_old + tanh(v + xp) * invT; publish
        float hold = hrow[h_glob];
        float hnew = hold + tanhf(v + xp) * invT;
        g_hp[(t + 1) & 1][(pod * PB + b_glob) * Hsz + h_glob] = hnew;

        __threadfence();   // release this thread's h store
        __syncwarp();
        if (lane == 0) atomicAdd(myflag, 1u);   // chunk complete at 16*(t+1)
    }

    // ---- Fused readout: out[b][o] = sum_k h_T[k][b]*W_out[o][k] + b_out[o]
    // Wait for all chunks' final publish, then rebuild layouts in freed smem.
    {
        const int target = 16 * Tlen;
        unsigned done;
        do {
            int v = (lane < PODB) ? (int)ldv(flagbase + lane * 32) : target;
            done = __all_sync(0xffffffffu, v >= target);
        } while (!done);
    }
    __syncthreads();                   // all warps done reading Wk/hsw

    float* Wo  = smem;                 // [512][32]
    float* hsT = smem + 512 * 32;      // [512][8] h-major
    {
        // hsT[k][b] from g_hp[0] (T even -> parity 0), coalesced per b row
        for (int b = 0; b < PB; b++)
            hsT[tid * PB + b] = __ldg(&g_hp[0][(pod * PB + b) * Hsz + tid]);
        // W_out slice transposed: Wo[k][32] for o in [ht*32, ht*32+32)
        const int lane_j = tid & 31, qg = tid >> 5;          // qg 0..15
        for (int q = qg; q < 128; q += 16) {
            float4 w = *(const float4*)&W_out[(ht * 32 + lane_j) * Hsz + 4 * q];
            Wo[(4*q+0)*32 + lane_j] = w.x;
            Wo[(4*q+1)*32 + lane_j] = w.y;
            Wo[(4*q+2)*32 + lane_j] = w.z;
            Wo[(4*q+3)*32 + lane_j] = w.w;
        }
    }
    __syncthreads();
    if (tid < 256) {
        const int b_ = tid & 7, og = tid >> 3;       // og 0..31
        float acc = 0.f;
        #pragma unroll 8
        for (int k = 0; k < Hsz; k++) {
            acc += hsT[k * PB + b_] * Wo[k * 32 + og];
        }
        out[(pod * PB + b_) * Osz + ht * 32 + og] = acc + b_out[ht * 32 + og];
    }
}

// ---------------------------------------------------------------------------
extern "C" void kernel_launch(void* const* d_in, const int* in_sizes, int n_in,
                              void* d_out, int out_size)
{
    const float* inputs = (const float*)d_in[0];
    const float* W_ih   = (const float*)d_in[1];
    const float* b_ih   = (const float*)d_in[2];
    const float* W_hh   = (const float*)d_in[3];
    const float* b_hh   = (const float*)d_in[4];
    const float* W_out  = (const float*)d_in[5];
    const float* b_out  = (const float*)d_in[6];
    const float* h0     = (const float*)d_in[7];
    float* out = (float*)d_out;

    const int SMEM_XP  = 8192 * 4 + 2 * 16 * XSROW * 8 + 1024 * 8;   // 73856 B
    const int SMEM_RNN = (64 * WROW + 16 * 2 * 512) * 4;             // 197632 B
    cudaFuncSetAttribute(xp_kernel,  cudaFuncAttributeMaxDynamicSharedMemorySize, SMEM_XP);
    cudaFuncSetAttribute(rnn_kernel, cudaFuncAttributeMaxDynamicSharedMemorySize, SMEM_RNN);

    xp_kernel<<<dim3(Tlen / TQ, NBT, Hsz / 32), 256, SMEM_XP>>>(inputs, W_ih, b_ih, b_hh);
    rnn_kernel<<<PODS * PODB, 512, SMEM_RNN>>>(W_hh, h0, W_out, b_out, out);
}